// round 2
// baseline (speedup 1.0000x reference)
#include <cuda_runtime.h>

// out[b,i,j,d] = x[b,i,j,d] + W[d, bin] + bias[d],  bin = clip(i-j,-31,31)+31
// B=2, L=512, D=128. x/out: 256 MB each (fp32). Pure HBM stream.
//
// Inputs (metadata order): d_in[0]=x (f32), d_in[1]=idx (i64, unused),
//                          d_in[2]=W (f32 [128,63]), d_in[3]=b (f32 [128])

#define L_DIM   512
#define D_DIM   128
#define NBINS   63
#define TOTAL_F4 (2 * L_DIM * L_DIM * (D_DIM / 4))   // 16,777,216

// Scratch table: relemb[bin][d] = W[d][bin] + b[d]  (63*128 floats = 32 KB)
__device__ float4 g_relemb[NBINS * (D_DIM / 4)];

__global__ void build_relemb_kernel(const float* __restrict__ W,
                                    const float* __restrict__ bias) {
    int t = blockIdx.x * blockDim.x + threadIdx.x;   // 0 .. 63*128-1
    if (t >= NBINS * D_DIM) return;
    int d   = t & (D_DIM - 1);
    int bin = t >> 7;                                 // t / 128
    float v = W[d * NBINS + bin] + bias[d];
    reinterpret_cast<float*>(g_relemb)[bin * D_DIM + d] = v;
}

__global__ __launch_bounds__(256)
void add_rel_kernel(const float4* __restrict__ x, float4* __restrict__ out) {
    int g = blockIdx.x * blockDim.x + threadIdx.x;    // float4 index
    // layout: g = ((b*L + i)*L + j)*32 + d4
    int d4  = g & 31;
    int row = g >> 5;                                 // b*L*L + i*L + j
    int j   = row & (L_DIM - 1);
    int i   = (row >> 9) & (L_DIM - 1);
    int rel = i - j;
    rel = max(-(NBINS / 2), min(NBINS / 2, rel));     // clip to [-31, 31]
    int bin = rel + NBINS / 2;                        // 0..62

    float4 xv = x[g];
    float4 rv = g_relemb[bin * 32 + d4];              // warp-coalesced L1 hit
    float4 ov;
    ov.x = xv.x + rv.x;
    ov.y = xv.y + rv.y;
    ov.z = xv.z + rv.z;
    ov.w = xv.w + rv.w;
    out[g] = ov;
}

extern "C" void kernel_launch(void* const* d_in, const int* in_sizes, int n_in,
                              void* d_out, int out_size) {
    const float* x    = (const float*)d_in[0];
    const float* W    = (const float*)d_in[2];
    const float* bias = (const float*)d_in[3];
    float* out        = (float*)d_out;

    build_relemb_kernel<<<(NBINS * D_DIM + 255) / 256, 256>>>(W, bias);

    add_rel_kernel<<<TOTAL_F4 / 256, 256>>>(
        (const float4*)x, (float4*)out);
}

// round 3
// speedup vs baseline: 1.0234x; 1.0234x over previous
#include <cuda_runtime.h>

// out[b,i,j,d] = x[b,i,j,d] + W[d, bin] + bias[d],  bin = clip(i-j,-31,31)+31
// B=2, L=512, D=128. x/out: 256 MB each (fp32). Pure HBM stream.
//
// Inputs (metadata order): d_in[0]=x (f32), d_in[1]=idx (i64, unused),
//                          d_in[2]=W (f32 [128,63]), d_in[3]=b (f32 [128])
//
// R2: 4 float4 per thread (front-batched independent loads -> MLP 4x),
//     streaming load/store hints, relemb table L1-resident.

#define L_DIM   512
#define D_DIM   128
#define NBINS   63
#define TOTAL_F4 (2 * L_DIM * L_DIM * (D_DIM / 4))   // 16,777,216
#define VPT 4                                         // float4 per thread
#define TPB 256

// Scratch table: relemb[bin][d] = W[d][bin] + b[d]  (63*128 floats = 32 KB)
__device__ float4 g_relemb[NBINS * (D_DIM / 4)];

__global__ void build_relemb_kernel(const float* __restrict__ W,
                                    const float* __restrict__ bias) {
    int d   = threadIdx.x;        // 0..127
    int bin = blockIdx.x;         // 0..62
    float v = W[d * NBINS + bin] + bias[d];
    reinterpret_cast<float*>(g_relemb)[bin * D_DIM + d] = v;
}

__global__ __launch_bounds__(TPB)
void add_rel_kernel(const float4* __restrict__ x, float4* __restrict__ out) {
    int base = blockIdx.x * (TPB * VPT) + threadIdx.x;

    // Front-batch the 4 independent global loads (MLP=4 per thread).
    float4 xv[VPT];
    #pragma unroll
    for (int k = 0; k < VPT; k++)
        xv[k] = __ldcs(&x[base + k * TPB]);

    float4 rv[VPT];
    #pragma unroll
    for (int k = 0; k < VPT; k++) {
        int g   = base + k * TPB;
        int d4  = g & 31;
        int row = g >> 5;                         // b*L*L + i*L + j
        int j   = row & (L_DIM - 1);
        int i   = (row >> 9) & (L_DIM - 1);
        int rel = i - j;
        rel = max(-(NBINS / 2), min(NBINS / 2, rel));
        int bin = rel + NBINS / 2;                // 0..62
        rv[k] = g_relemb[bin * 32 + d4];          // L1-resident table hit
    }

    #pragma unroll
    for (int k = 0; k < VPT; k++) {
        float4 ov;
        ov.x = xv[k].x + rv[k].x;
        ov.y = xv[k].y + rv[k].y;
        ov.z = xv[k].z + rv[k].z;
        ov.w = xv[k].w + rv[k].w;
        __stcs(&out[base + k * TPB], ov);
    }
}

extern "C" void kernel_launch(void* const* d_in, const int* in_sizes, int n_in,
                              void* d_out, int out_size) {
    const float* x    = (const float*)d_in[0];
    const float* W    = (const float*)d_in[2];
    const float* bias = (const float*)d_in[3];
    float* out        = (float*)d_out;

    build_relemb_kernel<<<NBINS, D_DIM>>>(W, bias);

    add_rel_kernel<<<TOTAL_F4 / (TPB * VPT), TPB>>>(
        (const float4*)x, (float4*)out);
}